// round 15
// baseline (speedup 1.0000x reference)
#include <cuda_runtime.h>
#include <cuda_bf16.h>
#include <math.h>

#define NVARS 8
#define NBINS 128
#define GRID  148
#define TPB   1024
#define NWARP (TPB / 32)
#define ROWPAD 9   // smem row stride in floats (9 coprime 32 -> conflict-free)

// Per-block partials (plain stores), arrival counters. Counters reset by the
// last block each run so graph replays start clean. Partials are overwritten
// unconditionally every run.
__device__ float    g_pmin[GRID * NVARS];
__device__ float    g_pmax[GRID * NVARS];
__device__ unsigned g_cnt0 = 0;   // phase-1 arrivals
__device__ unsigned g_cnt1 = 0;   // epilogue arrivals (reset owner)

// t_b = b/127 via PTX div.full.f32 — matches the reference's Triton-emitted
// division in the argmax fusion. DO NOT replace with __fdiv_rn.
__device__ __forceinline__ float t_divfull(int b) {
    float t;
    float fb = (float)b;
    asm("div.full.f32 %0, %1, %2;" : "=f"(t) : "f"(fb), "f"(127.0f));
    return t;
}

__device__ __forceinline__ unsigned poll_cg(const unsigned* p) {
    unsigned v;
    asm volatile("ld.global.cg.u32 %0, [%1];" : "=r"(v) : "l"(p) : "memory");
    return v;
}

__global__ void __launch_bounds__(TPB, 1)
fused_quantizer_kernel(const float* __restrict__ feats,
                       float* __restrict__ out_bins,
                       float* __restrict__ out_regs,
                       int nrows) {
    __shared__ float s_rows[TPB * ROWPAD];            // 36 KB: row cache
    __shared__ float s_mn[NWARP][NVARS];
    __shared__ float s_mx[NWARP][NVARS];
    __shared__ float s_fmin[NVARS], s_d[NVARS], s_step[NVARS], s_inv[NVARS];
    __shared__ float s_linC[NVARS][NBINS];  // criterion lin: fmin + d*t_divfull(b)
    __shared__ float s_linV[NVARS][NBINS];  // vals lin:      fmin + d*rn(b/127)

    const int tid  = threadIdx.x;
    const int bid  = blockIdx.x;
    const int lane = tid & 31;
    const int wid  = tid >> 5;
    const int gthreads = GRID * TPB;
    const int r0 = bid * TPB + tid;

    // ---- Phase 1: load rows (primary row -> SMEM), min/max reduce ----
    float mn[NVARS], mx[NVARS];
#pragma unroll
    for (int c = 0; c < NVARS; c++) { mn[c] = INFINITY; mx[c] = -INFINITY; }

    if (r0 < nrows) {
        const float4* p = reinterpret_cast<const float4*>(feats + (size_t)r0 * NVARS);
        float4 a = p[0];
        float4 b = p[1];
        float* sr = s_rows + tid * ROWPAD;
        sr[0] = a.x; sr[1] = a.y; sr[2] = a.z; sr[3] = a.w;
        sr[4] = b.x; sr[5] = b.y; sr[6] = b.z; sr[7] = b.w;
        mn[0] = fminf(mn[0], a.x); mx[0] = fmaxf(mx[0], a.x);
        mn[1] = fminf(mn[1], a.y); mx[1] = fmaxf(mx[1], a.y);
        mn[2] = fminf(mn[2], a.z); mx[2] = fmaxf(mx[2], a.z);
        mn[3] = fminf(mn[3], a.w); mx[3] = fmaxf(mx[3], a.w);
        mn[4] = fminf(mn[4], b.x); mx[4] = fmaxf(mx[4], b.x);
        mn[5] = fminf(mn[5], b.y); mx[5] = fmaxf(mx[5], b.y);
        mn[6] = fminf(mn[6], b.z); mx[6] = fmaxf(mx[6], b.z);
        mn[7] = fminf(mn[7], b.w); mx[7] = fmaxf(mx[7], b.w);
    }
    // Residual rows (nrows > gthreads), min/max only (cold for this dataset)
    for (int r = r0 + gthreads; r < nrows; r += gthreads) {
        const float4* p = reinterpret_cast<const float4*>(feats + (size_t)r * NVARS);
        float4 a = p[0];
        float4 b = p[1];
        mn[0] = fminf(mn[0], a.x); mx[0] = fmaxf(mx[0], a.x);
        mn[1] = fminf(mn[1], a.y); mx[1] = fmaxf(mx[1], a.y);
        mn[2] = fminf(mn[2], a.z); mx[2] = fmaxf(mx[2], a.z);
        mn[3] = fminf(mn[3], a.w); mx[3] = fmaxf(mx[3], a.w);
        mn[4] = fminf(mn[4], b.x); mx[4] = fmaxf(mx[4], b.x);
        mn[5] = fminf(mn[5], b.y); mx[5] = fmaxf(mx[5], b.y);
        mn[6] = fminf(mn[6], b.z); mx[6] = fmaxf(mx[6], b.z);
        mn[7] = fminf(mn[7], b.w); mx[7] = fmaxf(mx[7], b.w);
    }

#pragma unroll
    for (int off = 16; off > 0; off >>= 1) {
#pragma unroll
        for (int c = 0; c < NVARS; c++) {
            mn[c] = fminf(mn[c], __shfl_xor_sync(0xFFFFFFFFu, mn[c], off));
            mx[c] = fmaxf(mx[c], __shfl_xor_sync(0xFFFFFFFFu, mx[c], off));
        }
    }
    if (lane == 0) {
#pragma unroll
        for (int c = 0; c < NVARS; c++) { s_mn[wid][c] = mn[c]; s_mx[wid][c] = mx[c]; }
    }
    __syncthreads();

    // Warp 0 reduces 32 warp-slots -> per-block partials (plain stores)
    if (wid == 0) {
        int c = lane & 7, g = lane >> 3;
        float m = INFINITY, M = -INFINITY;
#pragma unroll
        for (int w = 0; w < 8; w++) {
            m = fminf(m, s_mn[g * 8 + w][c]);
            M = fmaxf(M, s_mx[g * 8 + w][c]);
        }
#pragma unroll
        for (int off = 8; off <= 16; off <<= 1) {
            m = fminf(m, __shfl_xor_sync(0xFFFFFFFFu, m, off));
            M = fmaxf(M, __shfl_xor_sync(0xFFFFFFFFu, M, off));
        }
        if (lane < NVARS) {
            g_pmin[bid * NVARS + lane] = m;
            g_pmax[bid * NVARS + lane] = M;
        }
        __threadfence();
        if (lane == 0) atomicAdd(&g_cnt0, 1u);  // single uniform-addr RED per block
    }

    // ---- Grid sync: poll with plain L2 loads (no RMW storm) ----
    if (tid == 0) {
        while (poll_cg(&g_cnt0) < (unsigned)GRID) { }
    }
    __syncthreads();
    __threadfence();

    // ---- Every block reduces the 148x8 partials itself (L2-hot, ~300cyc) ----
    if (wid < NVARS) {
        int c = wid;  // one warp per column
        float m = INFINITY, M = -INFINITY;
        for (int e = lane; e < GRID; e += 32) {
            m = fminf(m, g_pmin[e * NVARS + c]);
            M = fmaxf(M, g_pmax[e * NVARS + c]);
        }
#pragma unroll
        for (int off = 16; off > 0; off >>= 1) {
            m = fminf(m, __shfl_xor_sync(0xFFFFFFFFu, m, off));
            M = fmaxf(M, __shfl_xor_sync(0xFFFFFFFFu, M, off));
        }
        if (lane == 0) {
            float d = __fsub_rn(M, m);
            s_fmin[c] = m;
            s_d[c]    = d;
            float t1 = __fdiv_rn(1.0f, 127.0f);
            s_step[c] = __fsub_rn(__fadd_rn(m, __fmul_rn(d, t1)), m);
            s_inv[c]  = (d > 0.0f) ? (127.0f / d) : 0.0f;  // guess only
        }
    }
    __syncthreads();

    // ---- Build per-(col,bin) LUTs: 1024 threads = 8*128 ----
    {
        int c = tid >> 7;          // 0..7
        int b = tid & (NBINS - 1); // 0..127
        float fm = s_fmin[c], d = s_d[c];
        s_linC[c][b] = __fadd_rn(fm, __fmul_rn(d, t_divfull(b)));
        s_linV[c][b] = __fadd_rn(fm, __fmul_rn(d, __fdiv_rn((float)b, 127.0f)));
    }
    __syncthreads();

    // ---- Phase 2: quantize primary row from SMEM ----
    if (r0 < nrows) {
        const float* sr = s_rows + tid * ROWPAD;
        float bins[NVARS], regs[NVARS];
#pragma unroll
        for (int c = 0; c < NVARS; c++) {
            float feat = sr[c];
            int b = (int)((feat - s_fmin[c]) * s_inv[c]);
            b = max(0, min(NBINS - 1, b));
            while (b < NBINS - 1 &&
                   rintf(__fmul_rn(__fsub_rn(s_linC[c][b + 1], feat), 1000000.0f)) <= 0.0f) b++;
            while (b > 0 &&
                   !(rintf(__fmul_rn(__fsub_rn(s_linC[c][b], feat), 1000000.0f)) <= 0.0f)) b--;

            bins[c] = (float)b;
            regs[c] = __fdiv_rn(fmaxf(__fsub_rn(feat, s_linV[c][b]), 0.0f), s_step[c]);
        }
        float4* ob  = reinterpret_cast<float4*>(out_bins + (size_t)r0 * NVARS);
        float4* orr = reinterpret_cast<float4*>(out_regs + (size_t)r0 * NVARS);
        ob[0]  = make_float4(bins[0], bins[1], bins[2], bins[3]);
        ob[1]  = make_float4(bins[4], bins[5], bins[6], bins[7]);
        orr[0] = make_float4(regs[0], regs[1], regs[2], regs[3]);
        orr[1] = make_float4(regs[4], regs[5], regs[6], regs[7]);
    }
    // Residual rows: re-read from global (L2-hot; cold path for this dataset)
    for (int r = r0 + gthreads; r < nrows; r += gthreads) {
        const float4* p = reinterpret_cast<const float4*>(feats + (size_t)r * NVARS);
        float4 a = p[0];
        float4 b4 = p[1];
        float f[NVARS] = {a.x, a.y, a.z, a.w, b4.x, b4.y, b4.z, b4.w};
        float bins[NVARS], regs[NVARS];
#pragma unroll
        for (int c = 0; c < NVARS; c++) {
            float feat = f[c];
            int b = (int)((feat - s_fmin[c]) * s_inv[c]);
            b = max(0, min(NBINS - 1, b));
            while (b < NBINS - 1 &&
                   rintf(__fmul_rn(__fsub_rn(s_linC[c][b + 1], feat), 1000000.0f)) <= 0.0f) b++;
            while (b > 0 &&
                   !(rintf(__fmul_rn(__fsub_rn(s_linC[c][b], feat), 1000000.0f)) <= 0.0f)) b--;
            bins[c] = (float)b;
            regs[c] = __fdiv_rn(fmaxf(__fsub_rn(feat, s_linV[c][b]), 0.0f), s_step[c]);
        }
        float4* ob  = reinterpret_cast<float4*>(out_bins + (size_t)r * NVARS);
        float4* orr = reinterpret_cast<float4*>(out_regs + (size_t)r * NVARS);
        ob[0]  = make_float4(bins[0], bins[1], bins[2], bins[3]);
        ob[1]  = make_float4(bins[4], bins[5], bins[6], bins[7]);
        orr[0] = make_float4(regs[0], regs[1], regs[2], regs[3]);
        orr[1] = make_float4(regs[4], regs[5], regs[6], regs[7]);
    }

    // ---- Reset counters for the next graph replay ----
    __syncthreads();
    if (tid == 0) {
        unsigned t2 = atomicAdd(&g_cnt1, 1u);
        if (t2 == (unsigned)GRID - 1u) {
            g_cnt0 = 0u;
            __threadfence();
            g_cnt1 = 0u;
        }
    }
}

extern "C" void kernel_launch(void* const* d_in, const int* in_sizes, int n_in,
                              void* d_out, int out_size) {
    const float* feats = (const float*)d_in[0];
    int n = in_sizes[0];
    int nrows = n / NVARS;

    float* out = (float*)d_out;
    float* out_bins = out;       // first n elements: bins (as float32)
    float* out_regs = out + n;   // next n elements: regs

    fused_quantizer_kernel<<<GRID, TPB>>>(feats, out_bins, out_regs, nrows);
}

// round 16
// speedup vs baseline: 1.0890x; 1.0890x over previous
#include <cuda_runtime.h>
#include <cuda_bf16.h>
#include <math.h>

#define NVARS 8
#define NBINS 128
#define GRID  148
#define TPB   1024
#define NWARP 32
#define NSLOT 16   // 8 min slots + 8 max slots, ordered-uint

// Per-block partials [min x8 | max x8] (plain stores), arrival counters.
// Counters reset by the last block each run so graph replays start clean.
__device__ unsigned g_part[GRID * NSLOT];
__device__ unsigned g_cnt0 = 0;   // phase-1 arrivals
__device__ unsigned g_cnt1 = 0;   // epilogue arrivals (reset owner)

__device__ __forceinline__ unsigned f2o(float f) {
    unsigned u = __float_as_uint(f);
    return u ^ ((unsigned)((int)u >> 31) | 0x80000000u);
}
__device__ __forceinline__ float o2f(unsigned u) {
    unsigned b = (u & 0x80000000u) ? (u ^ 0x80000000u) : ~u;
    return __uint_as_float(b);
}

// t_b = b/127 via PTX div.full.f32 — matches the reference's Triton-emitted
// division in the argmax fusion. DO NOT replace with __fdiv_rn.
__device__ __forceinline__ float t_divfull(int b) {
    float t;
    float fb = (float)b;
    asm("div.full.f32 %0, %1, %2;" : "=f"(t) : "f"(fb), "f"(127.0f));
    return t;
}

__device__ __forceinline__ unsigned ld_acq(const unsigned* p) {
    unsigned v;
    asm volatile("ld.acquire.gpu.global.u32 %0, [%1];" : "=r"(v) : "l"(p) : "memory");
    return v;
}
__device__ __forceinline__ void red_rel_add(unsigned* p, unsigned v) {
    asm volatile("red.release.gpu.global.add.u32 [%0], %1;" :: "l"(p), "r"(v) : "memory");
}

// Eligibility: rint((linC - feat)*1e6) <= 0  ⟺  (linC - feat)*1e6 <= 0.5f
// (exact: rint(0.5)=0 half-even; the next f32 above 0.5 rounds to 1).
__device__ __forceinline__ bool elig(float linC, float feat) {
    return __fmul_rn(__fsub_rn(linC, feat), 1000000.0f) <= 0.5f;
}

__global__ void __launch_bounds__(TPB, 1)
fused_quantizer_kernel(const float* __restrict__ feats,
                       float* __restrict__ out_bins,
                       float* __restrict__ out_regs,
                       int nrows) {
    __shared__ unsigned s_part[NWARP][NSLOT];     // per-warp partials
    __shared__ unsigned s_final[NSLOT];           // block-final ordered-uints
    __shared__ float s_fmin[NVARS], s_d[NVARS], s_step[NVARS], s_inv[NVARS];
    __shared__ float s_linC[NVARS][NBINS];  // criterion lin: fmin + d*t_divfull(b)
    __shared__ float s_linV[NVARS][NBINS];  // vals lin:      fmin + d*rn(b/127)

    const int tid  = threadIdx.x;
    const int bid  = blockIdx.x;
    const int lane = tid & 31;
    const int wid  = tid >> 5;
    const int gthreads = GRID * TPB;
    const int r0 = bid * TPB + tid;

    // ---- Phase 1: load row into REGISTERS, ordered-uint min/max via REDUX ----
    float f[NVARS];
    unsigned umn[NVARS], umx[NVARS];
    bool have = (r0 < nrows);
    if (have) {
        const float4* p = reinterpret_cast<const float4*>(feats + (size_t)r0 * NVARS);
        float4 a = p[0];
        float4 b = p[1];
        f[0]=a.x; f[1]=a.y; f[2]=a.z; f[3]=a.w; f[4]=b.x; f[5]=b.y; f[6]=b.z; f[7]=b.w;
#pragma unroll
        for (int c = 0; c < NVARS; c++) { unsigned u = f2o(f[c]); umn[c] = u; umx[c] = u; }
    } else {
#pragma unroll
        for (int c = 0; c < NVARS; c++) { umn[c] = 0xFFFFFFFFu; umx[c] = 0u; }
    }
    // Residual rows (nrows > gthreads; cold for this dataset): min/max only.
    for (int r = r0 + gthreads; r < nrows; r += gthreads) {
        const float4* p = reinterpret_cast<const float4*>(feats + (size_t)r * NVARS);
        float4 a = p[0];
        float4 b = p[1];
        float g[NVARS] = {a.x,a.y,a.z,a.w,b.x,b.y,b.z,b.w};
#pragma unroll
        for (int c = 0; c < NVARS; c++) {
            unsigned u = f2o(g[c]);
            umn[c] = min(umn[c], u);
            umx[c] = max(umx[c], u);
        }
    }

#pragma unroll
    for (int c = 0; c < NVARS; c++) {
        umn[c] = __reduce_min_sync(0xFFFFFFFFu, umn[c]);
        umx[c] = __reduce_max_sync(0xFFFFFFFFu, umx[c]);
    }
    if (lane == 0) {
#pragma unroll
        for (int c = 0; c < NVARS; c++) {
            s_part[wid][c]         = umn[c];
            s_part[wid][NVARS + c] = umx[c];
        }
    }
    __syncthreads();

    // Warps 0..15: one slot each, reduce 32 warp-partials -> global partial.
    if (wid < NSLOT) {
        unsigned v = s_part[lane][wid];
        v = (wid < NVARS) ? __reduce_min_sync(0xFFFFFFFFu, v)
                          : __reduce_max_sync(0xFFFFFFFFu, v);
        if (lane == 0) g_part[bid * NSLOT + wid] = v;   // plain store
    }
    __syncthreads();
    if (tid == 0) red_rel_add(&g_cnt0, 1u);   // release: orders the stores above

    // ---- Grid sync: acquire-poll (all blocks resident by construction) ----
    if (tid == 0) {
        while (ld_acq(&g_cnt0) < (unsigned)GRID) { }
    }
    __syncthreads();

    // ---- Every block reduces 148 partials per slot (L2-hot, one REDUX) ----
    if (wid < NSLOT) {
        unsigned v = (wid < NVARS) ? 0xFFFFFFFFu : 0u;
        for (int e = lane; e < GRID; e += 32) {
            unsigned p = g_part[e * NSLOT + wid];
            v = (wid < NVARS) ? min(v, p) : max(v, p);
        }
        v = (wid < NVARS) ? __reduce_min_sync(0xFFFFFFFFu, v)
                          : __reduce_max_sync(0xFFFFFFFFu, v);
        if (lane == 0) s_final[wid] = v;
    }
    __syncthreads();

    // ---- Params + LUTs ----
    if (tid < NVARS) {
        float fm = o2f(s_final[tid]);
        float fM = o2f(s_final[NVARS + tid]);
        float d  = __fsub_rn(fM, fm);
        s_fmin[tid] = fm;
        s_d[tid]    = d;
        float t1 = __fdiv_rn(1.0f, 127.0f);
        s_step[tid] = __fsub_rn(__fadd_rn(fm, __fmul_rn(d, t1)), fm);
        s_inv[tid]  = (d > 0.0f) ? (127.0f / d) : 0.0f;  // guess only
    }
    __syncthreads();
    {
        int c = tid >> 7;          // 0..7
        int b = tid & (NBINS - 1); // 0..127
        float fm = s_fmin[c], d = s_d[c];
        s_linC[c][b] = __fadd_rn(fm, __fmul_rn(d, t_divfull(b)));
        s_linV[c][b] = __fadd_rn(fm, __fmul_rn(d, __fdiv_rn((float)b, 127.0f)));
    }
    __syncthreads();

    // ---- Phase 2: quantize from registers ----
    if (have) {
        float bins[NVARS], regs[NVARS];
#pragma unroll
        for (int c = 0; c < NVARS; c++) {
            float feat = f[c];
            int b = (int)((feat - s_fmin[c]) * s_inv[c]);
            b = max(0, min(NBINS - 1, b));
            while (b < NBINS - 1 && elig(s_linC[c][b + 1], feat)) b++;
            while (b > 0 && !elig(s_linC[c][b], feat)) b--;
            bins[c] = (float)b;
            regs[c] = __fdiv_rn(fmaxf(__fsub_rn(feat, s_linV[c][b]), 0.0f), s_step[c]);
        }
        float4* ob  = reinterpret_cast<float4*>(out_bins + (size_t)r0 * NVARS);
        float4* orr = reinterpret_cast<float4*>(out_regs + (size_t)r0 * NVARS);
        ob[0]  = make_float4(bins[0], bins[1], bins[2], bins[3]);
        ob[1]  = make_float4(bins[4], bins[5], bins[6], bins[7]);
        orr[0] = make_float4(regs[0], regs[1], regs[2], regs[3]);
        orr[1] = make_float4(regs[4], regs[5], regs[6], regs[7]);
    }
    // Residual rows: re-read from global (L2-hot; never runs for this dataset).
    for (int r = r0 + gthreads; r < nrows; r += gthreads) {
        const float4* p = reinterpret_cast<const float4*>(feats + (size_t)r * NVARS);
        float4 a = p[0];
        float4 b4 = p[1];
        float g[NVARS] = {a.x,a.y,a.z,a.w,b4.x,b4.y,b4.z,b4.w};
        float bins[NVARS], regs[NVARS];
#pragma unroll
        for (int c = 0; c < NVARS; c++) {
            float feat = g[c];
            int b = (int)((feat - s_fmin[c]) * s_inv[c]);
            b = max(0, min(NBINS - 1, b));
            while (b < NBINS - 1 && elig(s_linC[c][b + 1], feat)) b++;
            while (b > 0 && !elig(s_linC[c][b], feat)) b--;
            bins[c] = (float)b;
            regs[c] = __fdiv_rn(fmaxf(__fsub_rn(feat, s_linV[c][b]), 0.0f), s_step[c]);
        }
        float4* ob  = reinterpret_cast<float4*>(out_bins + (size_t)r * NVARS);
        float4* orr = reinterpret_cast<float4*>(out_regs + (size_t)r * NVARS);
        ob[0]  = make_float4(bins[0], bins[1], bins[2], bins[3]);
        ob[1]  = make_float4(bins[4], bins[5], bins[6], bins[7]);
        orr[0] = make_float4(regs[0], regs[1], regs[2], regs[3]);
        orr[1] = make_float4(regs[4], regs[5], regs[6], regs[7]);
    }

    // ---- Reset counters for the next graph replay ----
    __syncthreads();
    if (tid == 0) {
        unsigned t2 = atomicAdd(&g_cnt1, 1u);
        if (t2 == (unsigned)GRID - 1u) {
            g_cnt0 = 0u;
            __threadfence();
            g_cnt1 = 0u;
        }
    }
}

extern "C" void kernel_launch(void* const* d_in, const int* in_sizes, int n_in,
                              void* d_out, int out_size) {
    const float* feats = (const float*)d_in[0];
    int n = in_sizes[0];
    int nrows = n / NVARS;

    float* out = (float*)d_out;
    float* out_bins = out;       // first n elements: bins (as float32)
    float* out_regs = out + n;   // next n elements: regs

    fused_quantizer_kernel<<<GRID, TPB>>>(feats, out_bins, out_regs, nrows);
}

// round 17
// speedup vs baseline: 1.1078x; 1.0172x over previous
#include <cuda_runtime.h>
#include <cuda_bf16.h>
#include <math.h>

#define NVARS 8
#define NBINS 128
#define GRID  148
#define TPB   1024
#define NWARP 32
#define NSLOT 16   // 8 min slots + 8 max slots, ordered-uint

// rn(b/127) as compile-time constants (correctly-rounded fold, == __fdiv_rn).
#define T_(b) ((float)(b) / 127.0f)
#define R4_(b)  T_(b), T_(b+1), T_(b+2), T_(b+3)
#define R16_(b) R4_(b), R4_(b+4), R4_(b+8), R4_(b+12)
#define R64_(b) R16_(b), R16_(b+16), R16_(b+32), R16_(b+48)
__device__ __constant__ float c_trn[NBINS] = { R64_(0), R64_(64) };

// Per-block partials [min x8 | max x8] (plain stores), arrival counters.
__device__ unsigned g_part[GRID * NSLOT];
__device__ unsigned g_cnt0 = 0;   // phase-1 arrivals
__device__ unsigned g_cnt1 = 0;   // epilogue arrivals (reset owner)

__device__ __forceinline__ unsigned f2o(float f) {
    unsigned u = __float_as_uint(f);
    return u ^ ((unsigned)((int)u >> 31) | 0x80000000u);
}
__device__ __forceinline__ float o2f(unsigned u) {
    unsigned b = (u & 0x80000000u) ? (u ^ 0x80000000u) : ~u;
    return __uint_as_float(b);
}

// t_b = b/127 via PTX div.full.f32 — matches the reference's Triton-emitted
// division in the argmax fusion. DO NOT replace with __fdiv_rn.
__device__ __forceinline__ float t_divfull(int b) {
    float t;
    float fb = (float)b;
    asm("div.full.f32 %0, %1, %2;" : "=f"(t) : "f"(fb), "f"(127.0f));
    return t;
}

__device__ __forceinline__ unsigned ld_acq(const unsigned* p) {
    unsigned v;
    asm volatile("ld.acquire.gpu.global.u32 %0, [%1];" : "=r"(v) : "l"(p) : "memory");
    return v;
}
__device__ __forceinline__ void red_rel_add(unsigned* p, unsigned v) {
    asm volatile("red.release.gpu.global.add.u32 [%0], %1;" :: "l"(p), "r"(v) : "memory");
}

// Eligibility: rint((linC - feat)*1e6) <= 0  ⟺  (linC - feat)*1e6 <= 0.5f
// (exact: rint(0.5)=0 half-even; the next f32 above 0.5 rounds to 1).
__device__ __forceinline__ bool elig(float linC, float feat) {
    return __fmul_rn(__fsub_rn(linC, feat), 1000000.0f) <= 0.5f;
}

__global__ void __launch_bounds__(TPB, 1)
fused_quantizer_kernel(const float* __restrict__ feats,
                       float* __restrict__ out_bins,
                       float* __restrict__ out_regs,
                       int nrows) {
    __shared__ unsigned s_part[NWARP][NSLOT];
    __shared__ unsigned s_final[NSLOT];
    __shared__ float s_tC[NBINS];            // div.full t table (128 divs/block total)
    __shared__ float s_trn[NBINS];           // rn t table (constants)
    __shared__ float s_fmin[NVARS], s_d[NVARS], s_inv[NVARS], s_rstep[NVARS];
    __shared__ float s_linC[NVARS][NBINS];   // criterion lin: fmin + d*t_divfull(b)
    __shared__ float s_linV[NVARS][NBINS];   // vals lin:      fmin + d*rn(b/127)

    const int tid  = threadIdx.x;
    const int bid  = blockIdx.x;
    const int lane = tid & 31;
    const int wid  = tid >> 5;
    const int gthreads = GRID * TPB;
    const int r0 = bid * TPB + tid;

    // Data-independent t tables — overlaps the phase-1 load latency.
    if (tid < NBINS) {
        s_tC[tid]  = t_divfull(tid);
        s_trn[tid] = c_trn[tid];
    }

    // ---- Phase 1: load row into registers, ordered-uint min/max via REDUX ----
    float f[NVARS];
    unsigned umn[NVARS], umx[NVARS];
    bool have = (r0 < nrows);
    if (have) {
        const float4* p = reinterpret_cast<const float4*>(feats + (size_t)r0 * NVARS);
        float4 a = p[0];
        float4 b = p[1];
        f[0]=a.x; f[1]=a.y; f[2]=a.z; f[3]=a.w; f[4]=b.x; f[5]=b.y; f[6]=b.z; f[7]=b.w;
#pragma unroll
        for (int c = 0; c < NVARS; c++) { unsigned u = f2o(f[c]); umn[c] = u; umx[c] = u; }
    } else {
#pragma unroll
        for (int c = 0; c < NVARS; c++) { umn[c] = 0xFFFFFFFFu; umx[c] = 0u; }
    }
    // Residual rows (nrows > gthreads; cold for this dataset): min/max only.
    for (int r = r0 + gthreads; r < nrows; r += gthreads) {
        const float4* p = reinterpret_cast<const float4*>(feats + (size_t)r * NVARS);
        float4 a = p[0];
        float4 b = p[1];
        float g[NVARS] = {a.x,a.y,a.z,a.w,b.x,b.y,b.z,b.w};
#pragma unroll
        for (int c = 0; c < NVARS; c++) {
            unsigned u = f2o(g[c]);
            umn[c] = min(umn[c], u);
            umx[c] = max(umx[c], u);
        }
    }

#pragma unroll
    for (int c = 0; c < NVARS; c++) {
        umn[c] = __reduce_min_sync(0xFFFFFFFFu, umn[c]);
        umx[c] = __reduce_max_sync(0xFFFFFFFFu, umx[c]);
    }
    if (lane == 0) {
#pragma unroll
        for (int c = 0; c < NVARS; c++) {
            s_part[wid][c]         = umn[c];
            s_part[wid][NVARS + c] = umx[c];
        }
    }
    __syncthreads();

    // Warps 0..15: one slot each, reduce 32 warp-partials -> global partial.
    if (wid < NSLOT) {
        unsigned v = s_part[lane][wid];
        v = (wid < NVARS) ? __reduce_min_sync(0xFFFFFFFFu, v)
                          : __reduce_max_sync(0xFFFFFFFFu, v);
        if (lane == 0) g_part[bid * NSLOT + wid] = v;   // plain store
    }
    __syncthreads();
    if (tid == 0) red_rel_add(&g_cnt0, 1u);   // release: orders the stores above

    // ---- Grid sync: acquire-poll (all blocks resident by construction) ----
    if (tid == 0) {
        while (ld_acq(&g_cnt0) < (unsigned)GRID) { }
    }
    __syncthreads();

    // ---- Every block reduces 148 partials per slot (L2-hot) ----
    if (wid < NSLOT) {
        unsigned v = (wid < NVARS) ? 0xFFFFFFFFu : 0u;
        for (int e = lane; e < GRID; e += 32) {
            unsigned p = g_part[e * NSLOT + wid];
            v = (wid < NVARS) ? min(v, p) : max(v, p);
        }
        v = (wid < NVARS) ? __reduce_min_sync(0xFFFFFFFFu, v)
                          : __reduce_max_sync(0xFFFFFFFFu, v);
        if (lane == 0) s_final[wid] = v;
    }
    __syncthreads();

    // ---- Params (one div-ish op per column per block, not per element) ----
    if (tid < NVARS) {
        float fm = o2f(s_final[tid]);
        float fM = o2f(s_final[NVARS + tid]);
        float d  = __fsub_rn(fM, fm);
        s_fmin[tid] = fm;
        s_d[tid]    = d;
        // step = (fmin + d*rn(1/127)) - fmin, exactly as before
        float step = __fsub_rn(__fadd_rn(fm, __fmul_rn(d, c_trn[1])), fm);
        // regs tolerance is 1e-3; reciprocal-mul vs div.rn differs by ~1e-7 rel.
        s_rstep[tid] = (step != 0.0f) ? __frcp_rn(step) : 0.0f;
        s_inv[tid]   = (d > 0.0f) ? (127.0f / d) : 0.0f;  // guess only
    }
    __syncthreads();

    // ---- LUT build: pure mul+add from the t tables ----
    {
        int c = tid >> 7;          // 0..7
        int b = tid & (NBINS - 1); // 0..127
        float fm = s_fmin[c], d = s_d[c];
        s_linC[c][b] = __fadd_rn(fm, __fmul_rn(d, s_tC[b]));
        s_linV[c][b] = __fadd_rn(fm, __fmul_rn(d, s_trn[b]));
    }
    __syncthreads();

    // ---- Phase 2: quantize from registers (no divisions) ----
    if (have) {
        float bins[NVARS], regs[NVARS];
#pragma unroll
        for (int c = 0; c < NVARS; c++) {
            float feat = f[c];
            int b = (int)((feat - s_fmin[c]) * s_inv[c]);
            b = max(0, min(NBINS - 1, b));
            while (b < NBINS - 1 && elig(s_linC[c][b + 1], feat)) b++;
            while (b > 0 && !elig(s_linC[c][b], feat)) b--;
            bins[c] = (float)b;
            regs[c] = __fmul_rn(fmaxf(__fsub_rn(feat, s_linV[c][b]), 0.0f), s_rstep[c]);
        }
        float4* ob  = reinterpret_cast<float4*>(out_bins + (size_t)r0 * NVARS);
        float4* orr = reinterpret_cast<float4*>(out_regs + (size_t)r0 * NVARS);
        ob[0]  = make_float4(bins[0], bins[1], bins[2], bins[3]);
        ob[1]  = make_float4(bins[4], bins[5], bins[6], bins[7]);
        orr[0] = make_float4(regs[0], regs[1], regs[2], regs[3]);
        orr[1] = make_float4(regs[4], regs[5], regs[6], regs[7]);
    }
    // Residual rows (never runs for this dataset).
    for (int r = r0 + gthreads; r < nrows; r += gthreads) {
        const float4* p = reinterpret_cast<const float4*>(feats + (size_t)r * NVARS);
        float4 a = p[0];
        float4 b4 = p[1];
        float g[NVARS] = {a.x,a.y,a.z,a.w,b4.x,b4.y,b4.z,b4.w};
        float bins[NVARS], regs[NVARS];
#pragma unroll
        for (int c = 0; c < NVARS; c++) {
            float feat = g[c];
            int b = (int)((feat - s_fmin[c]) * s_inv[c]);
            b = max(0, min(NBINS - 1, b));
            while (b < NBINS - 1 && elig(s_linC[c][b + 1], feat)) b++;
            while (b > 0 && !elig(s_linC[c][b], feat)) b--;
            bins[c] = (float)b;
            regs[c] = __fmul_rn(fmaxf(__fsub_rn(feat, s_linV[c][b]), 0.0f), s_rstep[c]);
        }
        float4* ob  = reinterpret_cast<float4*>(out_bins + (size_t)r * NVARS);
        float4* orr = reinterpret_cast<float4*>(out_regs + (size_t)r * NVARS);
        ob[0]  = make_float4(bins[0], bins[1], bins[2], bins[3]);
        ob[1]  = make_float4(bins[4], bins[5], bins[6], bins[7]);
        orr[0] = make_float4(regs[0], regs[1], regs[2], regs[3]);
        orr[1] = make_float4(regs[4], regs[5], regs[6], regs[7]);
    }

    // ---- Reset counters for the next graph replay ----
    __syncthreads();
    if (tid == 0) {
        unsigned t2 = atomicAdd(&g_cnt1, 1u);
        if (t2 == (unsigned)GRID - 1u) {
            g_cnt0 = 0u;
            __threadfence();
            g_cnt1 = 0u;
        }
    }
}

extern "C" void kernel_launch(void* const* d_in, const int* in_sizes, int n_in,
                              void* d_out, int out_size) {
    const float* feats = (const float*)d_in[0];
    int n = in_sizes[0];
    int nrows = n / NVARS;

    float* out = (float*)d_out;
    float* out_bins = out;       // first n elements: bins (as float32)
    float* out_regs = out + n;   // next n elements: regs

    fused_quantizer_kernel<<<GRID, TPB>>>(feats, out_bins, out_regs, nrows);
}